// round 3
// baseline (speedup 1.0000x reference)
#include <cuda_runtime.h>
#include <cuda_bf16.h>

#define B_    64
#define L_    16384
#define D_    64
#define KSEL  256
#define TILE  128
#define ROWW  68
#define NBINS 4096
#define CAP   4096
#define NCHUNK 8                      // collect CTAs per batch
#define CHUNK (L_ / NCHUNK)           // 2048

__device__ float g_sim[B_ * L_];
__device__ unsigned g_hist[B_ * NBINS];          // zero-init; B1 re-zeroes
__device__ unsigned g_thr[B_];                   // threshold (u-space floor)
__device__ int g_cnt[B_];                        // zero-init; B1 re-zeroes
__device__ unsigned long long g_cand[B_ * CAP];

__device__ __forceinline__ unsigned f2u(float f) {
    unsigned b = __float_as_uint(f);
    return (b & 0x80000000u) ? ~b : (b | 0x80000000u);
}
__device__ __forceinline__ float u2f(unsigned u) {
    unsigned b = (u & 0x80000000u) ? (u & 0x7FFFFFFFu) : ~u;
    return __uint_as_float(b);
}

// ---------------------------------------------------------------------------
// Kernel A: similarities + per-batch 12-bit histogram (RED.global)
// ---------------------------------------------------------------------------
__global__ void __launch_bounds__(TILE) sim_kernel(
    const float* __restrict__ q,
    const float* __restrict__ keys,
    const float* __restrict__ gp)
{
    __shared__ __align__(16) float4 qsm[D_ / 4];
    __shared__ __align__(16) float  tile[TILE * ROWW];

    const int b   = blockIdx.y;
    const int t0  = blockIdx.x * TILE;
    const int tid = threadIdx.x;

    if (tid < D_ / 4)
        qsm[tid] = reinterpret_cast<const float4*>(q + b * D_)[tid];

    const float4* src = reinterpret_cast<const float4*>(
        keys + (size_t)b * L_ * D_ + (size_t)t0 * D_);
#pragma unroll
    for (int j = 0; j < 16; j++) {
        int f = j * TILE + tid;
        int l = f >> 4;
        int c = f & 15;
        unsigned dst = (unsigned)__cvta_generic_to_shared(&tile[l * ROWW + c * 4]);
        asm volatile("cp.async.cg.shared.global [%0], [%1], 16;\n"
                     :: "r"(dst), "l"(src + f));
    }
    asm volatile("cp.async.commit_group;\n");

    __syncthreads();

    float qq = 0.f;
#pragma unroll
    for (int i = 0; i < D_ / 4; i++) {
        float4 t = qsm[i];
        qq += t.x * t.x + t.y * t.y + t.z * t.z + t.w * t.w;
    }
    const float rq = gp[0] * rsqrtf(qq);

    asm volatile("cp.async.wait_group 0;\n");
    __syncthreads();

    float dot = 0.f, kk = 0.f;
#pragma unroll
    for (int i = 0; i < 16; i++) {
        float4 kv = *reinterpret_cast<const float4*>(&tile[tid * ROWW + i * 4]);
        float4 qv = qsm[i];
        dot += qv.x * kv.x + qv.y * kv.y + qv.z * kv.z + qv.w * kv.w;
        kk  += kv.x * kv.x + kv.y * kv.y + kv.z * kv.z + kv.w * kv.w;
    }
    float sim = dot * rq * rsqrtf(kk);
    g_sim[b * L_ + t0 + tid] = sim;
    atomicAdd(&g_hist[b * NBINS + (f2u(sim) >> 20)], 1u);
}

// ---------------------------------------------------------------------------
__device__ __forceinline__ int suffix_select(unsigned part, unsigned need,
                                             unsigned& above_out, int lane) {
    unsigned suf = part;
#pragma unroll
    for (int o = 1; o < 32; o <<= 1) {
        unsigned t = __shfl_down_sync(0xFFFFFFFFu, suf, o);
        if (lane + o < 32) suf += t;
    }
    unsigned above = suf - part;
    unsigned m = __ballot_sync(0xFFFFFFFFu,
                               (above < need) && (above + part >= need));
    int sel = __ffs(m) - 1;
    above_out = __shfl_sync(0xFFFFFFFFu, above, sel);
    return sel;
}

// ---------------------------------------------------------------------------
// B1: threshold from histogram; re-zero hist + candidate counter.
// ---------------------------------------------------------------------------
__global__ void __launch_bounds__(512) thresh_kernel()
{
    __shared__ unsigned hist[NBINS];
    const int b   = blockIdx.x;
    const int tid = threadIdx.x;

    for (int i = tid; i < NBINS; i += 512) {
        hist[i] = g_hist[b * NBINS + i];
        g_hist[b * NBINS + i] = 0;             // restore for next replay
    }
    if (tid == 0) g_cnt[b] = 0;
    __syncthreads();

    if (tid < 32) {
        const int lane = tid;
        unsigned part = 0;
        {
            int base = lane * 128;
            for (int j = 0; j < 128; j++) part += hist[base + j];
        }
        unsigned above1;
        int g1 = suffix_select(part, KSEL, above1, lane);
        int base2 = g1 * 128 + lane * 4;
        unsigned part2 = hist[base2] + hist[base2 + 1] +
                         hist[base2 + 2] + hist[base2 + 3];
        unsigned above2;
        int g2 = suffix_select(part2, KSEL - above1, above2, lane);
        int bin_base = g1 * 128 + g2 * 4;
        unsigned acc = above1 + above2;
        int bin = bin_base;
        for (int j = 3; j >= 0; j--) {
            unsigned h = hist[bin_base + j];
            if (acc + h >= KSEL) { bin = bin_base + j; break; }
            acc += h;
        }
        if (lane == 0) g_thr[b] = ((unsigned)bin) << 20;
    }
}

// ---------------------------------------------------------------------------
// B2: parallel candidate collect. grid (B_, NCHUNK), 512 thr.
// Warp-aggregated global atomics into per-batch list.
// ---------------------------------------------------------------------------
__global__ void __launch_bounds__(512) collect_kernel()
{
    const int b    = blockIdx.x;
    const int base = blockIdx.y * CHUNK;
    const int tid  = threadIdx.x;
    const unsigned lo = g_thr[b];

#pragma unroll
    for (int r = 0; r < CHUNK / 512; r++) {
        int i = base + r * 512 + tid;
        unsigned u = f2u(g_sim[b * L_ + i]);
        bool take = (u >= lo);
        unsigned m = __ballot_sync(0xFFFFFFFFu, take);
        if (m) {
            int lane = tid & 31;
            int nbelow = __popc(m & ((1u << lane) - 1));
            int cnt = __popc(m);
            int basepos;
            if (lane == __ffs(m) - 1)
                basepos = atomicAdd(&g_cnt[b], cnt);
            basepos = __shfl_sync(0xFFFFFFFFu, basepos, __ffs(m) - 1);
            if (take) {
                int p = basepos + nbelow;
                if (p < CAP)
                    g_cand[b * CAP + p] =
                        ((unsigned long long)u << 32) | (unsigned)(~i);
            }
        }
    }
}

// ---------------------------------------------------------------------------
// B3: sort candidates, softmax, gather. 64 CTAs x 512 thr.
// ---------------------------------------------------------------------------
__global__ void __launch_bounds__(512) sort_kernel(
    const float* __restrict__ values,
    float* __restrict__ out)
{
    __shared__ __align__(16) unsigned long long cand[CAP];
    __shared__ float s_e[KSEL];
    __shared__ float s_sum;

    const int b   = blockIdx.x;
    const int tid = threadIdx.x;
    const int T   = 512;

    int n = g_cnt[b];
    if (n > CAP) n = CAP;
    int sz = KSEL;
    while (sz < n) sz <<= 1;

    for (int i = tid; i < sz; i += T)
        cand[i] = (i < n) ? g_cand[b * CAP + i] : 0ull;
    __syncthreads();

    // bitonic sort descending by (u, ~idx): desc value, asc index on ties
    for (int kk = 2; kk <= sz; kk <<= 1) {
        for (int j = kk >> 1; j > 0; j >>= 1) {
            for (int i = tid; i < sz; i += T) {
                int ixj = i ^ j;
                if (ixj > i) {
                    unsigned long long a = cand[i], c = cand[ixj];
                    bool desc = (i & kk) == 0;
                    if (desc ? (a < c) : (a > c)) {
                        cand[i] = c; cand[ixj] = a;
                    }
                }
            }
            __syncthreads();
        }
    }

    float maxs = u2f((unsigned)(cand[0] >> 32));
    if (tid < KSEL) {
        float s = u2f((unsigned)(cand[tid] >> 32));
        s_e[tid] = expf(s - maxs);
    }
    __syncthreads();
    if (tid < 32) {
        float acc = 0.f;
        for (int j = tid; j < KSEL; j += 32) acc += s_e[j];
#pragma unroll
        for (int o = 16; o > 0; o >>= 1)
            acc += __shfl_xor_sync(0xFFFFFFFFu, acc, o);
        if (tid == 0) s_sum = acc;
    }
    __syncthreads();
    if (tid < KSEL) {
        int idx = (int)(~(unsigned)cand[tid]);
        out[b * KSEL + tid]             = values[b * L_ + idx];
        out[B_ * KSEL + b * KSEL + tid] = s_e[tid] / s_sum;
    }
}

// ---------------------------------------------------------------------------
extern "C" void kernel_launch(void* const* d_in, const int* in_sizes, int n_in,
                              void* d_out, int out_size)
{
    const float* q      = (const float*)d_in[0];
    const float* keys   = (const float*)d_in[1];
    const float* values = (const float*)d_in[2];
    const float* g      = (const float*)d_in[3];
    float* out = (float*)d_out;

    (void)in_sizes; (void)n_in; (void)out_size;

    dim3 gridA(L_ / TILE, B_);
    sim_kernel<<<gridA, TILE>>>(q, keys, g);

    thresh_kernel<<<B_, 512>>>();

    dim3 gridC(B_, NCHUNK);
    collect_kernel<<<gridC, 512>>>();

    sort_kernel<<<B_, 512>>>(values, out);
}